// round 16
// baseline (speedup 1.0000x reference)
#include <cuda_runtime.h>
#include <cuda_fp16.h>
#include <cstdint>
#include <math.h>

#define Bb 4
#define Tt 2048
#define Cc 1024
#define Hh 16
#define Dd 64

// log2(e) / sqrt(Dd) — folded into Q at GEMM1 epilogue
#define QSCALE 0.1803368801f

// Scratch (allocation-free rule: device globals), all fp16
__device__ __half g_qkv[(size_t)Bb * Tt * 3 * Cc];
__device__ __half g_y[(size_t)Bb * Tt * Cc];
__device__ __half g_xh[(size_t)Bb * Tt * Cc];     // x converted
__device__ __half g_wah[(size_t)Cc * 3 * Cc];     // W_attn^T [N][K] half
__device__ __half g_wph[(size_t)Cc * Cc];         // W_proj^T [N][K] half

// ---------------------------------------------------------------------------
// Helpers
// ---------------------------------------------------------------------------
__device__ __forceinline__ void mma_f16(float c[4],
    uint32_t a0, uint32_t a1, uint32_t a2, uint32_t a3, uint32_t b0, uint32_t b1)
{
    asm volatile(
        "mma.sync.aligned.m16n8k16.row.col.f32.f16.f16.f32 "
        "{%0,%1,%2,%3}, {%4,%5,%6,%7}, {%8,%9}, {%0,%1,%2,%3};\n"
        : "+f"(c[0]), "+f"(c[1]), "+f"(c[2]), "+f"(c[3])
        : "r"(a0), "r"(a1), "r"(a2), "r"(a3), "r"(b0), "r"(b1));
}

__device__ __forceinline__ void ldsm_x4(uint32_t& r0, uint32_t& r1, uint32_t& r2, uint32_t& r3, uint32_t a) {
    asm volatile("ldmatrix.sync.aligned.m8n8.x4.shared.b16 {%0,%1,%2,%3}, [%4];"
        : "=r"(r0), "=r"(r1), "=r"(r2), "=r"(r3) : "r"(a));
}
__device__ __forceinline__ void ldsm_x2_t(uint32_t& r0, uint32_t& r1, uint32_t a) {
    asm volatile("ldmatrix.sync.aligned.m8n8.x2.trans.shared.b16 {%0,%1}, [%2];"
        : "=r"(r0), "=r"(r1) : "r"(a));
}

__device__ __forceinline__ void cp_async16(void* smem_dst, const void* gmem_src) {
    uint32_t s = (uint32_t)__cvta_generic_to_shared(smem_dst);
    asm volatile("cp.async.cg.shared.global [%0], [%1], 16;\n" :: "r"(s), "l"(gmem_src));
}
#define CP_COMMIT() asm volatile("cp.async.commit_group;\n" ::: "memory")
#define CP_WAIT(n)  asm volatile("cp.async.wait_group %0;\n" :: "n"(n) : "memory")

__device__ __forceinline__ uint32_t cvta_s(const void* p) {
    return (uint32_t)__cvta_generic_to_shared(p);
}

__device__ __forceinline__ uint32_t pack_h2(float a, float b) {
    __half2 h = __floats2half2_rn(a, b);
    return *(uint32_t*)&h;
}

__device__ __forceinline__ float ex2(float x) {
    float r;
    asm("ex2.approx.f32 %0, %1;" : "=f"(r) : "f"(x));
    return r;
}

__device__ __forceinline__ void store_pair(__half* p, float a, float b) {
    *(uint32_t*)p = pack_h2(a, b);
}
__device__ __forceinline__ void store_pair(float* p, float a, float b) {
    *(float2*)p = make_float2(a, b);
}

// ---------------------------------------------------------------------------
// fp32 -> fp16 conversion kernels
// ---------------------------------------------------------------------------
__global__ __launch_bounds__(256) void tohalf_kernel(
    const float4* __restrict__ in, uint2* __restrict__ out, int n4)
{
    int i = blockIdx.x * blockDim.x + threadIdx.x;
    if (i < n4) {
        float4 v = in[i];
        __half2 h0 = __floats2half2_rn(v.x, v.y);
        __half2 h1 = __floats2half2_rn(v.z, v.w);
        out[i] = make_uint2(*(uint32_t*)&h0, *(uint32_t*)&h1);
    }
}

// in [K][N] fp32 -> out [N][K] fp16
__global__ __launch_bounds__(256) void transpose_tohalf_kernel(
    const float* __restrict__ in, __half* __restrict__ out, int K, int N)
{
    __shared__ float t[32][33];
    int n0 = blockIdx.x * 32, k0 = blockIdx.y * 32;
    int tx = threadIdx.x & 31, ty = threadIdx.x >> 5;
    #pragma unroll
    for (int i = ty; i < 32; i += 8) t[i][tx] = in[(size_t)(k0 + i) * N + n0 + tx];
    __syncthreads();
    #pragma unroll
    for (int i = ty; i < 32; i += 8) out[(size_t)(n0 + i) * K + k0 + tx] = __float2half_rn(t[tx][i]);
}

// ---------------------------------------------------------------------------
// fp16 tensor-core GEMM + bias. Single __syncthreads per ktile; prefetch
// issued post-barrier so cp.async overlaps the full compute span.
// QLIM: columns c < QLIM multiplied by QSCALE after bias (GEMM1 Q-fold).
// ---------------------------------------------------------------------------
#define GAS 72                        // halves per smem row (64 + 8 pad)
#define GTILE_H (128 * GAS)           // 9216 halves per operand tile
#define GSTAGE_H (2 * GTILE_H)        // A + B per stage
#define GEMM_SMEM (2 * GSTAGE_H * 2)  // bytes: 73728

template <typename OutT>
__global__ __launch_bounds__(128, 2) void h_gemm_kernel(
    const __half* __restrict__ A, const __half* __restrict__ Bt,
    const float* __restrict__ bias, OutT* __restrict__ C,
    int M, int N, int K, int qlim)
{
    extern __shared__ __half smh[];
    __half* As[2] = { smh,           smh + GSTAGE_H };
    __half* Bs[2] = { smh + GTILE_H, smh + GSTAGE_H + GTILE_H };

    const int tid = threadIdx.x;
    const int lane = tid & 31, wid = tid >> 5;
    const int warp_m = wid >> 1, warp_n = wid & 1;
    const int gid = lane >> 2, tg = lane & 3;
    const int lj = lane & 7, lb = lane >> 3;

    const int bm = blockIdx.y * 128, bn = blockIdx.x * 128;
    const int nt_k = K >> 6;   // ktiles of 64
    const float osc = (bn < qlim) ? QSCALE : 1.0f;   // tile-uniform (qlim % 128 == 0)

    auto load_tile = [&](int buf, int kt) {
        const __half* Ag = A  + (size_t)bm * K + kt * 64;
        const __half* Bg = Bt + (size_t)bn * K + kt * 64;
        #pragma unroll
        for (int p = 0; p < 8; p++) {
            int idx = tid + 128 * p;
            int r = idx >> 3, c = (idx & 7) << 3;
            cp_async16(&As[buf][r * GAS + c], Ag + (size_t)r * K + c);
            cp_async16(&Bs[buf][r * GAS + c], Bg + (size_t)r * K + c);
        }
    };

    float acc[4][8][4];
    #pragma unroll
    for (int mt = 0; mt < 4; mt++)
        #pragma unroll
        for (int nt = 0; nt < 8; nt++)
            #pragma unroll
            for (int r = 0; r < 4; r++) acc[mt][nt][r] = 0.f;

    load_tile(0, 0);
    CP_COMMIT();

    const int a_row_off = (lb & 1) * 8 + lj;
    const int a_col_off = (lb >> 1) * 8;
    const int b_row_off = (lb >> 1) * 8 + lj;
    const int b_col_off = (lb & 1) * 8;

    for (int kt = 0; kt < nt_k; kt++) {
        const int cur = kt & 1;
        CP_WAIT(0);
        __syncthreads();   // tile kt resident; all warps done computing kt-1

        if (kt + 1 < nt_k) { load_tile(cur ^ 1, kt + 1); CP_COMMIT(); }

        const __half* as = As[cur];
        const __half* bs = Bs[cur];

        #pragma unroll
        for (int kk = 0; kk < 4; kk++) {
            const int k16 = kk << 4;
            uint32_t af[4][4];
            #pragma unroll
            for (int mt = 0; mt < 4; mt++) {
                const int r = warp_m * 64 + mt * 16 + a_row_off;
                ldsm_x4(af[mt][0], af[mt][1], af[mt][2], af[mt][3],
                        cvta_s(&as[r * GAS + k16 + a_col_off]));
            }
            uint32_t bf[8][2];
            #pragma unroll
            for (int np = 0; np < 4; np++) {
                const int r = warp_n * 64 + np * 16 + b_row_off;
                ldsm_x4(bf[2 * np][0], bf[2 * np][1], bf[2 * np + 1][0], bf[2 * np + 1][1],
                        cvta_s(&bs[r * GAS + k16 + b_col_off]));
            }
            #pragma unroll
            for (int mt = 0; mt < 4; mt++)
                #pragma unroll
                for (int nt = 0; nt < 8; nt++)
                    mma_f16(acc[mt][nt], af[mt][0], af[mt][1], af[mt][2], af[mt][3],
                            bf[nt][0], bf[nt][1]);
        }
    }

    #pragma unroll
    for (int mt = 0; mt < 4; mt++) {
        #pragma unroll
        for (int nt = 0; nt < 8; nt++) {
            int r = bm + warp_m * 64 + mt * 16 + gid;
            int c = bn + warp_n * 64 + nt * 8 + (tg << 1);
            float b0 = bias[c], b1 = bias[c + 1];
            store_pair(C + (size_t)r * N + c,
                       (acc[mt][nt][0] + b0) * osc, (acc[mt][nt][1] + b1) * osc);
            store_pair(C + (size_t)(r + 8) * N + c,
                       (acc[mt][nt][2] + b0) * osc, (acc[mt][nt][3] + b1) * osc);
        }
    }
}

// ---------------------------------------------------------------------------
// fp16 flash attention, BQ=64, register-P, base-2 softmax (Q pre-scaled).
// l kept lane-partial during the loop (alpha is tg-uniform); reduced once at
// the end. qb reversed (heaviest CTAs first).
// ---------------------------------------------------------------------------
#define FST 72
#define FTILE_H (64 * FST)                  // 4608
#define FLASH_SMEM (5 * FTILE_H * 2)        // 46080 bytes

__global__ __launch_bounds__(128) void flash_h_kernel(
    const __half* __restrict__ qkv, __half* __restrict__ y)
{
    extern __shared__ __half sh[];
    __half* Qs    = sh;
    __half* Ks[2] = { sh + FTILE_H,     sh + 2 * FTILE_H };
    __half* Vs[2] = { sh + 3 * FTILE_H, sh + 4 * FTILE_H };

    const int qb = gridDim.x - 1 - blockIdx.x;   // reversed: big tiles first
    const int h = blockIdx.y, b = blockIdx.z;
    const int tid = threadIdx.x;
    const int lane = tid & 31, w = tid >> 5;
    const int gid = lane >> 2, tg = lane & 3;
    const int lj = lane & 7, lb = lane >> 3;

    const size_t rs = (size_t)3 * Cc;   // 3072 halves
    const __half* qbase = qkv + ((size_t)(b * Tt) + (size_t)qb * 64) * rs + h * Dd;

    auto load_kv = [&](int st, int kb) {
        const __half* kbase = qkv + ((size_t)(b * Tt) + (size_t)kb * 64) * rs + Cc + h * Dd;
        const __half* vbase = kbase + Cc;
        #pragma unroll
        for (int p = 0; p < 4; p++) {
            int idx = tid + 128 * p;
            int r = idx >> 3, c = (idx & 7) << 3;
            cp_async16(&Ks[st][r * FST + c], kbase + (size_t)r * rs + c);
            cp_async16(&Vs[st][r * FST + c], vbase + (size_t)r * rs + c);
        }
    };

    #pragma unroll
    for (int p = 0; p < 4; p++) {
        int idx = tid + 128 * p;
        int r = idx >> 3, c = (idx & 7) << 3;
        cp_async16(&Qs[r * FST + c], qbase + (size_t)r * rs + c);
    }
    load_kv(0, 0);
    CP_COMMIT();
    CP_WAIT(0);
    __syncthreads();

    uint32_t qa[4][4];
    {
        const int arow = w * 16 + (lb & 1) * 8 + lj;
        const int akof = (lb >> 1) * 8;
        #pragma unroll
        for (int kk = 0; kk < 4; kk++)
            ldsm_x4(qa[kk][0], qa[kk][1], qa[kk][2], qa[kk][3],
                    cvta_s(&Qs[arow * FST + kk * 16 + akof]));
    }

    float o[8][4];
    #pragma unroll
    for (int nt = 0; nt < 8; nt++)
        #pragma unroll
        for (int r = 0; r < 4; r++) o[nt][r] = 0.f;
    float m0 = -INFINITY, m1 = -INFINITY, l0 = 0.f, l1 = 0.f;  // l lane-partial

    for (int kb = 0; kb <= qb; kb++) {
        const int cur = kb & 1;
        if (kb < qb) { load_kv(cur ^ 1, kb + 1); CP_COMMIT(); }

        // ---- S = Q K^T (log2 domain) ----
        float s[8][4];
        #pragma unroll
        for (int nt = 0; nt < 8; nt++)
            #pragma unroll
            for (int r = 0; r < 4; r++) s[nt][r] = 0.f;

        {
            const __half* Kc = Ks[cur];
            const int brow8 = (lb >> 1) * 8 + lj;
            const int bkof  = (lb & 1) * 8;
            #pragma unroll
            for (int nt2 = 0; nt2 < 8; nt2 += 2) {
                #pragma unroll
                for (int kk = 0; kk < 4; kk++) {
                    uint32_t b0, b1, b2, b3;
                    ldsm_x4(b0, b1, b2, b3,
                            cvta_s(&Kc[(nt2 * 8 + brow8) * FST + kk * 16 + bkof]));
                    mma_f16(s[nt2],     qa[kk][0], qa[kk][1], qa[kk][2], qa[kk][3], b0, b1);
                    mma_f16(s[nt2 + 1], qa[kk][0], qa[kk][1], qa[kk][2], qa[kk][3], b2, b3);
                }
            }
        }

        // ---- causal mask (diag tile only) ----
        if (kb == qb) {
            const int ql0 = w * 16 + gid, ql1 = ql0 + 8;
            #pragma unroll
            for (int nt = 0; nt < 8; nt++) {
                const int kl = nt * 8 + (tg << 1);
                if (kl     > ql0) s[nt][0] = -INFINITY;
                if (kl + 1 > ql0) s[nt][1] = -INFINITY;
                if (kl     > ql1) s[nt][2] = -INFINITY;
                if (kl + 1 > ql1) s[nt][3] = -INFINITY;
            }
        }

        // ---- online softmax, base-2; max reduced, sums stay lane-partial ----
        float mx0 = -INFINITY, mx1 = -INFINITY;
        #pragma unroll
        for (int nt = 0; nt < 8; nt++) {
            mx0 = fmaxf(mx0, fmaxf(s[nt][0], s[nt][1]));
            mx1 = fmaxf(mx1, fmaxf(s[nt][2], s[nt][3]));
        }
        mx0 = fmaxf(mx0, __shfl_xor_sync(0xffffffffu, mx0, 1));
        mx0 = fmaxf(mx0, __shfl_xor_sync(0xffffffffu, mx0, 2));
        mx1 = fmaxf(mx1, __shfl_xor_sync(0xffffffffu, mx1, 1));
        mx1 = fmaxf(mx1, __shfl_xor_sync(0xffffffffu, mx1, 2));

        const float nm0 = fmaxf(m0, mx0);
        const float nm1 = fmaxf(m1, mx1);
        const float a0 = ex2(m0 - nm0);
        const float a1 = ex2(m1 - nm1);
        m0 = nm0; m1 = nm1;

        float sum0 = 0.f, sum1 = 0.f;
        #pragma unroll
        for (int nt = 0; nt < 8; nt++) {
            s[nt][0] = ex2(s[nt][0] - nm0);
            s[nt][1] = ex2(s[nt][1] - nm0);
            s[nt][2] = ex2(s[nt][2] - nm1);
            s[nt][3] = ex2(s[nt][3] - nm1);
            sum0 += s[nt][0] + s[nt][1];
            sum1 += s[nt][2] + s[nt][3];
        }
        l0 = l0 * a0 + sum0;   // lane-partial
        l1 = l1 * a1 + sum1;

        #pragma unroll
        for (int nt = 0; nt < 8; nt++) {
            o[nt][0] *= a0; o[nt][1] *= a0;
            o[nt][2] *= a1; o[nt][3] *= a1;
        }

        // ---- P: repack S accumulator fragments directly into A-operands ----
        uint32_t pa[4][4];
        #pragma unroll
        for (int kk = 0; kk < 4; kk++) {
            pa[kk][0] = pack_h2(s[2 * kk][0],     s[2 * kk][1]);
            pa[kk][1] = pack_h2(s[2 * kk][2],     s[2 * kk][3]);
            pa[kk][2] = pack_h2(s[2 * kk + 1][0], s[2 * kk + 1][1]);
            pa[kk][3] = pack_h2(s[2 * kk + 1][2], s[2 * kk + 1][3]);
        }

        // ---- O += P @ V ----
        {
            const __half* Vc = Vs[cur];
            const int vrow8 = (lb & 1) * 8 + lj;
            #pragma unroll
            for (int nt = 0; nt < 8; nt++) {
                #pragma unroll
                for (int kk = 0; kk < 4; kk++) {
                    uint32_t b0, b1;
                    ldsm_x2_t(b0, b1, cvta_s(&Vc[(kk * 16 + vrow8) * FST + nt * 8]));
                    mma_f16(o[nt], pa[kk][0], pa[kk][1], pa[kk][2], pa[kk][3], b0, b1);
                }
            }
        }

        if (kb < qb) { CP_WAIT(0); __syncthreads(); }
    }

    // ---- final l reduction across tg lanes, then normalize + write ----
    l0 += __shfl_xor_sync(0xffffffffu, l0, 1);
    l0 += __shfl_xor_sync(0xffffffffu, l0, 2);
    l1 += __shfl_xor_sync(0xffffffffu, l1, 1);
    l1 += __shfl_xor_sync(0xffffffffu, l1, 2);
    const float inv0 = 1.f / l0;
    const float inv1 = 1.f / l1;
    const int r0g = qb * 64 + w * 16 + gid;
    __half* y0 = y + ((size_t)(b * Tt) + r0g) * Cc + h * Dd;
    __half* y1 = y0 + 8 * Cc;
    #pragma unroll
    for (int nt = 0; nt < 8; nt++) {
        const int c = nt * 8 + (tg << 1);
        store_pair(y0 + c, o[nt][0] * inv0, o[nt][1] * inv0);
        store_pair(y1 + c, o[nt][2] * inv1, o[nt][3] * inv1);
    }
}

// ---------------------------------------------------------------------------
extern "C" void kernel_launch(void* const* d_in, const int* in_sizes, int n_in,
                              void* d_out, int out_size)
{
    const float* x  = (const float*)d_in[0];
    const float* Wa = (const float*)d_in[1];
    const float* ba = (const float*)d_in[2];
    const float* Wp = (const float*)d_in[3];
    const float* bp = (const float*)d_in[4];
    float* out = (float*)d_out;

    __half *qkv, *y, *xh, *wah, *wph;
    cudaGetSymbolAddress((void**)&qkv, g_qkv);
    cudaGetSymbolAddress((void**)&y,   g_y);
    cudaGetSymbolAddress((void**)&xh,  g_xh);
    cudaGetSymbolAddress((void**)&wah, g_wah);
    cudaGetSymbolAddress((void**)&wph, g_wph);

    const int M = Bb * Tt;           // 8192
    const int N1 = 3 * Cc;           // 3072

    cudaFuncSetAttribute(h_gemm_kernel<__half>, cudaFuncAttributeMaxDynamicSharedMemorySize, GEMM_SMEM);
    cudaFuncSetAttribute(h_gemm_kernel<float>,  cudaFuncAttributeMaxDynamicSharedMemorySize, GEMM_SMEM);
    cudaFuncSetAttribute(flash_h_kernel, cudaFuncAttributeMaxDynamicSharedMemorySize, FLASH_SMEM);

    {
        int n4x = (M * Cc) / 4;
        tohalf_kernel<<<(n4x + 255) / 256, 256>>>((const float4*)x, (uint2*)xh, n4x);
        transpose_tohalf_kernel<<<dim3(N1 / 32, Cc / 32), 256>>>(Wa, wah, Cc, N1);
        transpose_tohalf_kernel<<<dim3(Cc / 32, Cc / 32), 256>>>(Wp, wph, Cc, Cc);
    }

    // GEMM1: qkv = x @ W_attn + b_attn; Q columns (c<1024) scaled by log2e/8
    h_gemm_kernel<__half><<<dim3(N1 / 128, M / 128), 128, GEMM_SMEM>>>(xh, wah, ba, qkv, M, N1, Cc, Cc);

    // Flash attention (fp16, BQ=64, register-P, base-2 softmax, reversed qb)
    flash_h_kernel<<<dim3(Tt / 64, Hh, Bb), 128, FLASH_SMEM>>>(qkv, y);

    // GEMM2: out = y @ W_proj + b_proj  (fp32 out, no column scaling)
    h_gemm_kernel<float><<<dim3(Cc / 128, M / 128), 128, GEMM_SMEM>>>(y, wph, bp, out, M, Cc, Cc, 0);
}

// round 17
// speedup vs baseline: 1.0780x; 1.0780x over previous
#include <cuda_runtime.h>
#include <cuda_fp16.h>
#include <cstdint>
#include <math.h>

#define Bb 4
#define Tt 2048
#define Cc 1024
#define Hh 16
#define Dd 64

// log2(e) / sqrt(Dd) — folded into Q at GEMM1 epilogue
#define QSCALE 0.1803368801f

// Scratch (allocation-free rule: device globals), all fp16
__device__ __half g_qkv[(size_t)Bb * Tt * 3 * Cc];
__device__ __half g_y[(size_t)Bb * Tt * Cc];
__device__ __half g_xh[(size_t)Bb * Tt * Cc];     // x converted
__device__ __half g_wah[(size_t)Cc * 3 * Cc];     // W_attn^T [N][K] half
__device__ __half g_wph[(size_t)Cc * Cc];         // W_proj^T [N][K] half

// ---------------------------------------------------------------------------
// Helpers
// ---------------------------------------------------------------------------
__device__ __forceinline__ void mma_f16(float c[4],
    uint32_t a0, uint32_t a1, uint32_t a2, uint32_t a3, uint32_t b0, uint32_t b1)
{
    asm volatile(
        "mma.sync.aligned.m16n8k16.row.col.f32.f16.f16.f32 "
        "{%0,%1,%2,%3}, {%4,%5,%6,%7}, {%8,%9}, {%0,%1,%2,%3};\n"
        : "+f"(c[0]), "+f"(c[1]), "+f"(c[2]), "+f"(c[3])
        : "r"(a0), "r"(a1), "r"(a2), "r"(a3), "r"(b0), "r"(b1));
}

__device__ __forceinline__ void ldsm_x4(uint32_t& r0, uint32_t& r1, uint32_t& r2, uint32_t& r3, uint32_t a) {
    asm volatile("ldmatrix.sync.aligned.m8n8.x4.shared.b16 {%0,%1,%2,%3}, [%4];"
        : "=r"(r0), "=r"(r1), "=r"(r2), "=r"(r3) : "r"(a));
}
__device__ __forceinline__ void ldsm_x4_t(uint32_t& r0, uint32_t& r1, uint32_t& r2, uint32_t& r3, uint32_t a) {
    asm volatile("ldmatrix.sync.aligned.m8n8.x4.trans.shared.b16 {%0,%1,%2,%3}, [%4];"
        : "=r"(r0), "=r"(r1), "=r"(r2), "=r"(r3) : "r"(a));
}

__device__ __forceinline__ void cp_async16(void* smem_dst, const void* gmem_src) {
    uint32_t s = (uint32_t)__cvta_generic_to_shared(smem_dst);
    asm volatile("cp.async.cg.shared.global [%0], [%1], 16;\n" :: "r"(s), "l"(gmem_src));
}
#define CP_COMMIT() asm volatile("cp.async.commit_group;\n" ::: "memory")
#define CP_WAIT(n)  asm volatile("cp.async.wait_group %0;\n" :: "n"(n) : "memory")

__device__ __forceinline__ uint32_t cvta_s(const void* p) {
    return (uint32_t)__cvta_generic_to_shared(p);
}

__device__ __forceinline__ uint32_t pack_h2(float a, float b) {
    __half2 h = __floats2half2_rn(a, b);
    return *(uint32_t*)&h;
}

__device__ __forceinline__ float ex2(float x) {
    float r;
    asm("ex2.approx.f32 %0, %1;" : "=f"(r) : "f"(x));
    return r;
}

__device__ __forceinline__ void store_pair(__half* p, float a, float b) {
    *(uint32_t*)p = pack_h2(a, b);
}
__device__ __forceinline__ void store_pair(float* p, float a, float b) {
    *(float2*)p = make_float2(a, b);
}

// ---------------------------------------------------------------------------
// fp32 -> fp16 conversion kernels
// ---------------------------------------------------------------------------
__global__ __launch_bounds__(256) void tohalf_kernel(
    const float4* __restrict__ in, uint2* __restrict__ out, int n4)
{
    int i = blockIdx.x * blockDim.x + threadIdx.x;
    if (i < n4) {
        float4 v = in[i];
        __half2 h0 = __floats2half2_rn(v.x, v.y);
        __half2 h1 = __floats2half2_rn(v.z, v.w);
        out[i] = make_uint2(*(uint32_t*)&h0, *(uint32_t*)&h1);
    }
}

// Fused weight transpose: [K][N] fp32 -> [N][K] fp16 for BOTH W_attn and
// W_proj in one launch. Block-uniform source select on n0.
__global__ __launch_bounds__(256) void transpose_both_kernel(
    const float* __restrict__ Wa, __half* __restrict__ wah,
    const float* __restrict__ Wp, __half* __restrict__ wph,
    int K, int Na, int Np)
{
    __shared__ float t[32][33];
    int n0g = blockIdx.x * 32, k0 = blockIdx.y * 32;
    const float* in; __half* out; int N, n0;
    if (n0g < Na) { in = Wa; out = wah; N = Na; n0 = n0g; }
    else          { in = Wp; out = wph; N = Np; n0 = n0g - Na; }
    int tx = threadIdx.x & 31, ty = threadIdx.x >> 5;
    #pragma unroll
    for (int i = ty; i < 32; i += 8) t[i][tx] = in[(size_t)(k0 + i) * N + n0 + tx];
    __syncthreads();
    #pragma unroll
    for (int i = ty; i < 32; i += 8) out[(size_t)(n0 + i) * K + k0 + tx] = __float2half_rn(t[tx][i]);
}

// ---------------------------------------------------------------------------
// fp16 tensor-core GEMM + bias (R15-exact mainloop — verified plateau).
// QLIM: columns c < QLIM multiplied by QSCALE after bias (GEMM1 Q-fold).
// ---------------------------------------------------------------------------
#define GAS 72                        // halves per smem row (64 + 8 pad)
#define GTILE_H (128 * GAS)           // 9216 halves per operand tile
#define GSTAGE_H (2 * GTILE_H)        // A + B per stage
#define GEMM_SMEM (2 * GSTAGE_H * 2)  // bytes: 73728

template <typename OutT>
__global__ __launch_bounds__(128, 2) void h_gemm_kernel(
    const __half* __restrict__ A, const __half* __restrict__ Bt,
    const float* __restrict__ bias, OutT* __restrict__ C,
    int M, int N, int K, int qlim)
{
    extern __shared__ __half smh[];
    __half* As[2] = { smh,           smh + GSTAGE_H };
    __half* Bs[2] = { smh + GTILE_H, smh + GSTAGE_H + GTILE_H };

    const int tid = threadIdx.x;
    const int lane = tid & 31, wid = tid >> 5;
    const int warp_m = wid >> 1, warp_n = wid & 1;
    const int gid = lane >> 2, tg = lane & 3;
    const int lj = lane & 7, lb = lane >> 3;

    const int bm = blockIdx.y * 128, bn = blockIdx.x * 128;
    const int nt_k = K >> 6;   // ktiles of 64
    const float osc = (bn < qlim) ? QSCALE : 1.0f;   // tile-uniform (qlim % 128 == 0)

    auto load_tile = [&](int buf, int kt) {
        const __half* Ag = A  + (size_t)bm * K + kt * 64;
        const __half* Bg = Bt + (size_t)bn * K + kt * 64;
        #pragma unroll
        for (int p = 0; p < 8; p++) {
            int idx = tid + 128 * p;
            int r = idx >> 3, c = (idx & 7) << 3;
            cp_async16(&As[buf][r * GAS + c], Ag + (size_t)r * K + c);
            cp_async16(&Bs[buf][r * GAS + c], Bg + (size_t)r * K + c);
        }
    };

    float acc[4][8][4];
    #pragma unroll
    for (int mt = 0; mt < 4; mt++)
        #pragma unroll
        for (int nt = 0; nt < 8; nt++)
            #pragma unroll
            for (int r = 0; r < 4; r++) acc[mt][nt][r] = 0.f;

    load_tile(0, 0);
    CP_COMMIT();

    const int a_row_off = (lb & 1) * 8 + lj;
    const int a_col_off = (lb >> 1) * 8;
    const int b_row_off = (lb >> 1) * 8 + lj;
    const int b_col_off = (lb & 1) * 8;

    for (int kt = 0; kt < nt_k; kt++) {
        const int cur = kt & 1;
        if (kt + 1 < nt_k) { load_tile(cur ^ 1, kt + 1); CP_COMMIT(); CP_WAIT(1); }
        else               { CP_WAIT(0); }
        __syncthreads();

        const __half* as = As[cur];
        const __half* bs = Bs[cur];

        #pragma unroll
        for (int kk = 0; kk < 4; kk++) {
            const int k16 = kk << 4;
            uint32_t af[4][4];
            #pragma unroll
            for (int mt = 0; mt < 4; mt++) {
                const int r = warp_m * 64 + mt * 16 + a_row_off;
                ldsm_x4(af[mt][0], af[mt][1], af[mt][2], af[mt][3],
                        cvta_s(&as[r * GAS + k16 + a_col_off]));
            }
            uint32_t bf[8][2];
            #pragma unroll
            for (int np = 0; np < 4; np++) {
                const int r = warp_n * 64 + np * 16 + b_row_off;
                ldsm_x4(bf[2 * np][0], bf[2 * np][1], bf[2 * np + 1][0], bf[2 * np + 1][1],
                        cvta_s(&bs[r * GAS + k16 + b_col_off]));
            }
            #pragma unroll
            for (int mt = 0; mt < 4; mt++)
                #pragma unroll
                for (int nt = 0; nt < 8; nt++)
                    mma_f16(acc[mt][nt], af[mt][0], af[mt][1], af[mt][2], af[mt][3],
                            bf[nt][0], bf[nt][1]);
        }
        __syncthreads();
    }

    #pragma unroll
    for (int mt = 0; mt < 4; mt++) {
        #pragma unroll
        for (int nt = 0; nt < 8; nt++) {
            int r = bm + warp_m * 64 + mt * 16 + gid;
            int c = bn + warp_n * 64 + nt * 8 + (tg << 1);
            float b0 = bias[c], b1 = bias[c + 1];
            store_pair(C + (size_t)r * N + c,
                       (acc[mt][nt][0] + b0) * osc, (acc[mt][nt][1] + b1) * osc);
            store_pair(C + (size_t)(r + 8) * N + c,
                       (acc[mt][nt][2] + b0) * osc, (acc[mt][nt][3] + b1) * osc);
        }
    }
}

// ---------------------------------------------------------------------------
// fp16 flash attention, BQ=64, register-P, base-2 softmax (Q pre-scaled).
// V fragments via ldmatrix.x4.trans (one op = two n8 blocks, both k8 halves).
// l lane-partial in-loop, reduced at epilogue. qb reversed.
// ---------------------------------------------------------------------------
#define FST 72
#define FTILE_H (64 * FST)                  // 4608
#define FLASH_SMEM (5 * FTILE_H * 2)        // 46080 bytes

__global__ __launch_bounds__(128) void flash_h_kernel(
    const __half* __restrict__ qkv, __half* __restrict__ y)
{
    extern __shared__ __half sh[];
    __half* Qs    = sh;
    __half* Ks[2] = { sh + FTILE_H,     sh + 2 * FTILE_H };
    __half* Vs[2] = { sh + 3 * FTILE_H, sh + 4 * FTILE_H };

    const int qb = gridDim.x - 1 - blockIdx.x;   // reversed: big tiles first
    const int h = blockIdx.y, b = blockIdx.z;
    const int tid = threadIdx.x;
    const int lane = tid & 31, w = tid >> 5;
    const int gid = lane >> 2, tg = lane & 3;
    const int lj = lane & 7, lb = lane >> 3;

    const size_t rs = (size_t)3 * Cc;   // 3072 halves
    const __half* qbase = qkv + ((size_t)(b * Tt) + (size_t)qb * 64) * rs + h * Dd;

    auto load_kv = [&](int st, int kb) {
        const __half* kbase = qkv + ((size_t)(b * Tt) + (size_t)kb * 64) * rs + Cc + h * Dd;
        const __half* vbase = kbase + Cc;
        #pragma unroll
        for (int p = 0; p < 4; p++) {
            int idx = tid + 128 * p;
            int r = idx >> 3, c = (idx & 7) << 3;
            cp_async16(&Ks[st][r * FST + c], kbase + (size_t)r * rs + c);
            cp_async16(&Vs[st][r * FST + c], vbase + (size_t)r * rs + c);
        }
    };

    #pragma unroll
    for (int p = 0; p < 4; p++) {
        int idx = tid + 128 * p;
        int r = idx >> 3, c = (idx & 7) << 3;
        cp_async16(&Qs[r * FST + c], qbase + (size_t)r * rs + c);
    }
    load_kv(0, 0);
    CP_COMMIT();
    CP_WAIT(0);
    __syncthreads();

    uint32_t qa[4][4];
    {
        const int arow = w * 16 + (lb & 1) * 8 + lj;
        const int akof = (lb >> 1) * 8;
        #pragma unroll
        for (int kk = 0; kk < 4; kk++)
            ldsm_x4(qa[kk][0], qa[kk][1], qa[kk][2], qa[kk][3],
                    cvta_s(&Qs[arow * FST + kk * 16 + akof]));
    }

    float o[8][4];
    #pragma unroll
    for (int nt = 0; nt < 8; nt++)
        #pragma unroll
        for (int r = 0; r < 4; r++) o[nt][r] = 0.f;
    float m0 = -INFINITY, m1 = -INFINITY, l0 = 0.f, l1 = 0.f;  // l lane-partial

    // V ldmatrix.x4.trans address components (R13 GEMM-B validated mapping)
    const int v_row_off = (lb & 1) * 8 + lj;   // k-row within k16 block
    const int v_col_off = (lb >> 1) * 8;       // n8 select within 16 cols

    for (int kb = 0; kb <= qb; kb++) {
        const int cur = kb & 1;
        if (kb < qb) { load_kv(cur ^ 1, kb + 1); CP_COMMIT(); }

        // ---- S = Q K^T (log2 domain) ----
        float s[8][4];
        #pragma unroll
        for (int nt = 0; nt < 8; nt++)
            #pragma unroll
            for (int r = 0; r < 4; r++) s[nt][r] = 0.f;

        {
            const __half* Kc = Ks[cur];
            const int brow8 = (lb >> 1) * 8 + lj;
            const int bkof  = (lb & 1) * 8;
            #pragma unroll
            for (int nt2 = 0; nt2 < 8; nt2 += 2) {
                #pragma unroll
                for (int kk = 0; kk < 4; kk++) {
                    uint32_t b0, b1, b2, b3;
                    ldsm_x4(b0, b1, b2, b3,
                            cvta_s(&Kc[(nt2 * 8 + brow8) * FST + kk * 16 + bkof]));
                    mma_f16(s[nt2],     qa[kk][0], qa[kk][1], qa[kk][2], qa[kk][3], b0, b1);
                    mma_f16(s[nt2 + 1], qa[kk][0], qa[kk][1], qa[kk][2], qa[kk][3], b2, b3);
                }
            }
        }

        // ---- causal mask (diag tile only) ----
        if (kb == qb) {
            const int ql0 = w * 16 + gid, ql1 = ql0 + 8;
            #pragma unroll
            for (int nt = 0; nt < 8; nt++) {
                const int kl = nt * 8 + (tg << 1);
                if (kl     > ql0) s[nt][0] = -INFINITY;
                if (kl + 1 > ql0) s[nt][1] = -INFINITY;
                if (kl     > ql1) s[nt][2] = -INFINITY;
                if (kl + 1 > ql1) s[nt][3] = -INFINITY;
            }
        }

        // ---- online softmax, base-2; max reduced, l stays lane-partial ----
        float mx0 = -INFINITY, mx1 = -INFINITY;
        #pragma unroll
        for (int nt = 0; nt < 8; nt++) {
            mx0 = fmaxf(mx0, fmaxf(s[nt][0], s[nt][1]));
            mx1 = fmaxf(mx1, fmaxf(s[nt][2], s[nt][3]));
        }
        mx0 = fmaxf(mx0, __shfl_xor_sync(0xffffffffu, mx0, 1));
        mx0 = fmaxf(mx0, __shfl_xor_sync(0xffffffffu, mx0, 2));
        mx1 = fmaxf(mx1, __shfl_xor_sync(0xffffffffu, mx1, 1));
        mx1 = fmaxf(mx1, __shfl_xor_sync(0xffffffffu, mx1, 2));

        const float nm0 = fmaxf(m0, mx0);
        const float nm1 = fmaxf(m1, mx1);
        const float a0 = ex2(m0 - nm0);
        const float a1 = ex2(m1 - nm1);
        m0 = nm0; m1 = nm1;

        float sum0 = 0.f, sum1 = 0.f;
        #pragma unroll
        for (int nt = 0; nt < 8; nt++) {
            s[nt][0] = ex2(s[nt][0] - nm0);
            s[nt][1] = ex2(s[nt][1] - nm0);
            s[nt][2] = ex2(s[nt][2] - nm1);
            s[nt][3] = ex2(s[nt][3] - nm1);
            sum0 += s[nt][0] + s[nt][1];
            sum1 += s[nt][2] + s[nt][3];
        }
        l0 = l0 * a0 + sum0;
        l1 = l1 * a1 + sum1;

        #pragma unroll
        for (int nt = 0; nt < 8; nt++) {
            o[nt][0] *= a0; o[nt][1] *= a0;
            o[nt][2] *= a1; o[nt][3] *= a1;
        }

        // ---- P: repack S accumulator fragments directly into A-operands ----
        uint32_t pa[4][4];
        #pragma unroll
        for (int kk = 0; kk < 4; kk++) {
            pa[kk][0] = pack_h2(s[2 * kk][0],     s[2 * kk][1]);
            pa[kk][1] = pack_h2(s[2 * kk][2],     s[2 * kk][3]);
            pa[kk][2] = pack_h2(s[2 * kk + 1][0], s[2 * kk + 1][1]);
            pa[kk][3] = pack_h2(s[2 * kk + 1][2], s[2 * kk + 1][3]);
        }

        // ---- O += P @ V (V B-frags via x4.trans: two n8 blocks per op) ----
        {
            const __half* Vc = Vs[cur];
            #pragma unroll
            for (int nt2 = 0; nt2 < 8; nt2 += 2) {
                #pragma unroll
                for (int kk = 0; kk < 4; kk++) {
                    uint32_t b0, b1, b2, b3;
                    ldsm_x4_t(b0, b1, b2, b3,
                              cvta_s(&Vc[(kk * 16 + v_row_off) * FST + nt2 * 8 + v_col_off]));
                    mma_f16(o[nt2],     pa[kk][0], pa[kk][1], pa[kk][2], pa[kk][3], b0, b1);
                    mma_f16(o[nt2 + 1], pa[kk][0], pa[kk][1], pa[kk][2], pa[kk][3], b2, b3);
                }
            }
        }

        if (kb < qb) { CP_WAIT(0); __syncthreads(); }
    }

    // ---- final l reduction across tg lanes, then normalize + write ----
    l0 += __shfl_xor_sync(0xffffffffu, l0, 1);
    l0 += __shfl_xor_sync(0xffffffffu, l0, 2);
    l1 += __shfl_xor_sync(0xffffffffu, l1, 1);
    l1 += __shfl_xor_sync(0xffffffffu, l1, 2);
    const float inv0 = 1.f / l0;
    const float inv1 = 1.f / l1;
    const int r0g = qb * 64 + w * 16 + gid;
    __half* y0 = y + ((size_t)(b * Tt) + r0g) * Cc + h * Dd;
    __half* y1 = y0 + 8 * Cc;
    #pragma unroll
    for (int nt = 0; nt < 8; nt++) {
        const int c = nt * 8 + (tg << 1);
        store_pair(y0 + c, o[nt][0] * inv0, o[nt][1] * inv0);
        store_pair(y1 + c, o[nt][2] * inv1, o[nt][3] * inv1);
    }
}

// ---------------------------------------------------------------------------
extern "C" void kernel_launch(void* const* d_in, const int* in_sizes, int n_in,
                              void* d_out, int out_size)
{
    const float* x  = (const float*)d_in[0];
    const float* Wa = (const float*)d_in[1];
    const float* ba = (const float*)d_in[2];
    const float* Wp = (const float*)d_in[3];
    const float* bp = (const float*)d_in[4];
    float* out = (float*)d_out;

    __half *qkv, *y, *xh, *wah, *wph;
    cudaGetSymbolAddress((void**)&qkv, g_qkv);
    cudaGetSymbolAddress((void**)&y,   g_y);
    cudaGetSymbolAddress((void**)&xh,  g_xh);
    cudaGetSymbolAddress((void**)&wah, g_wah);
    cudaGetSymbolAddress((void**)&wph, g_wph);

    const int M = Bb * Tt;           // 8192
    const int N1 = 3 * Cc;           // 3072

    cudaFuncSetAttribute(h_gemm_kernel<__half>, cudaFuncAttributeMaxDynamicSharedMemorySize, GEMM_SMEM);
    cudaFuncSetAttribute(h_gemm_kernel<float>,  cudaFuncAttributeMaxDynamicSharedMemorySize, GEMM_SMEM);
    cudaFuncSetAttribute(flash_h_kernel, cudaFuncAttributeMaxDynamicSharedMemorySize, FLASH_SMEM);

    {
        int n4x = (M * Cc) / 4;
        tohalf_kernel<<<(n4x + 255) / 256, 256>>>((const float4*)x, (uint2*)xh, n4x);
        transpose_both_kernel<<<dim3((N1 + Cc) / 32, Cc / 32), 256>>>(Wa, wah, Wp, wph, Cc, N1, Cc);
    }

    // GEMM1: qkv = x @ W_attn + b_attn; Q columns (c<1024) scaled by log2e/8
    h_gemm_kernel<__half><<<dim3(N1 / 128, M / 128), 128, GEMM_SMEM>>>(xh, wah, ba, qkv, M, N1, Cc, Cc);

    // Flash attention (fp16, BQ=64, register-P, base-2 softmax, reversed qb)
    flash_h_kernel<<<dim3(Tt / 64, Hh, Bb), 128, FLASH_SMEM>>>(qkv, y);

    // GEMM2: out = y @ W_proj + b_proj  (fp32 out, no column scaling)
    h_gemm_kernel<float><<<dim3(Cc / 128, M / 128), 128, GEMM_SMEM>>>(y, wph, bp, out, M, Cc, Cc, 0);
}